// round 10
// baseline (speedup 1.0000x reference)
#include <cuda_runtime.h>

// Bench shape: N=1024, IND=OUTD=32, E=8192
#define NN    1024
#define DIM   32
#define EBASE 8192
#define EMAXP (EBASE + 3 * NN)     // padded-CSR worst case (rows rounded to 4)
#define NTHR  1024
#define NWARP 32
#define ZROW  (NN * DIM)           // dummy (always-zero) row offset (scaled)

// Shared-memory layout (float-index offsets into one dynamic allocation)
#define OFF_SX   0                            // [32800] tX rows + zero row
#define OFF_SMK  32800                        // [1056] mask
#define OFF_SW   (OFF_SMK + 1056)             // [1024] W copy
#define OFF_SOFF (OFF_SW + 1024)              // [1032] (int) CSR offsets
#define OFF_SIDX (OFF_SOFF + 1032)            // [EMAXP] (int) colidx*DIM
#define SMEM_FLOATS (OFF_SIDX + EMAXP)        // 47176 floats ≈ 188.7 KB

extern __shared__ float smem[];

// CSR scratch (device globals: allocation is forbidden)
__device__ int g_offsets[NN + 1];
__device__ int g_colidx[EMAXP];    // col * DIM (dummy pad -> ZROW)

// ---- packed f32x2 helpers (Blackwell; ptxas won't auto-fuse) --------------
__device__ __forceinline__ unsigned long long pack_f2(float lo, float hi) {
    unsigned long long r;
    asm("mov.b64 %0, {%1, %2};" : "=l"(r) : "f"(lo), "f"(hi));
    return r;
}
__device__ __forceinline__ void ffma2(unsigned long long& d,
                                      unsigned long long a,
                                      unsigned long long b) {
    asm("fma.rn.f32x2 %0, %1, %2, %0;" : "+l"(d) : "l"(a), "l"(b));
}
__device__ __forceinline__ float hsum_f2(unsigned long long v) {
    float lo, hi;
    asm("mov.b64 {%0, %1}, %2;" : "=f"(lo), "=f"(hi) : "l"(v));
    return lo + hi;
}

// ---------------------------------------------------------------------------
// Destination-keyed CSR, rows padded to multiples of 4 with dummy index ZROW.
// ---------------------------------------------------------------------------
__global__ void build_csr_kernel(const int* __restrict__ erow,
                                 const int* __restrict__ ecol, int E) {
    __shared__ int scnt[NN];
    __shared__ int sscan[NN];
    __shared__ int scur[NN];
    const int t = threadIdx.x;

    scnt[t] = 0;
    __syncthreads();
    for (int e = t; e < E; e += NN) atomicAdd(&scnt[erow[e]], 1);
    __syncthreads();

    const int padded = (scnt[t] + 3) & ~3;
    sscan[t] = padded;
    __syncthreads();
    #pragma unroll
    for (int d = 1; d < NN; d <<= 1) {
        int x = sscan[t];
        int y = (t >= d) ? sscan[t - d] : 0;
        __syncthreads();
        sscan[t] = x + y;
        __syncthreads();
    }
    const int incl = sscan[t];
    g_offsets[t + 1] = incl;
    if (t == 0) g_offsets[0] = 0;
    scur[t] = incl - padded;
    __syncthreads();

    for (int e = t; e < E; e += NN) {
        int r = erow[e];
        int p = atomicAdd(&scur[r], 1);
        g_colidx[p] = ecol[e] * DIM;
    }
    __syncthreads();
    for (int p = scur[t]; p < incl; p++) g_colidx[p] = ZROW;
}

// ---------------------------------------------------------------------------
// Phase 1 (own frame): tX[r] = X[r]@W + b  in place, active rows only.
// Warp-per-row, lane-per-output, broadcast LDS.128 + packed FFMA2.
// Masked rows stay exactly zero, so the gather's bias term
// b * (sum_e m[col]) emerges automatically.
// ---------------------------------------------------------------------------
__device__ __noinline__ void phase_mlp(int lane, int warp, float breg) {
    float*       sX  = smem + OFF_SX;
    const float* smk = smem + OFF_SMK;
    const float* sW  = smem + OFF_SW;

    unsigned long long wp[DIM / 2];        // 32 regs, live only in this frame
    #pragma unroll
    for (int q = 0; q < DIM / 2; q++)
        wp[q] = pack_f2(sW[(2 * q) * DIM + lane], sW[(2 * q + 1) * DIM + lane]);

    #pragma unroll 1
    for (int r = warp; r < NN; r += NWARP) {
        if (smk[r] == 0.0f) continue;      // warp-uniform skip
        const ulonglong2* xr = (const ulonglong2*)(sX + r * DIM);
        unsigned long long a0 = 0ULL, a1 = 0ULL;
        #pragma unroll
        for (int q = 0; q < 8; q++) {
            ulonglong2 v = xr[q];          // broadcast LDS.128
            ffma2(a0, v.x, wp[2 * q]);
            ffma2(a1, v.y, wp[2 * q + 1]);
        }
        float val = hsum_f2(a0) + hsum_f2(a1) + breg;
        __syncwarp();                      // all lanes done reading row r
        sX[r * DIM + lane] = val;          // in-place overwrite
    }
}

// ---------------------------------------------------------------------------
// Phase 2 (own frame): out[i,j] = m[j] * sum_e tX[col_e]
// Warp-per-j, lane-per-dim, 4-unrolled gathers (dummy edges hit zero row).
// ---------------------------------------------------------------------------
__device__ __noinline__ void phase_gather(float* __restrict__ out, int i,
                                          int lane, int warp) {
    const float* sX   = smem + OFF_SX;
    const float* smk  = smem + OFF_SMK;
    const int*   soff = (const int*)(smem + OFF_SOFF);
    const int*   sidx = (const int*)(smem + OFF_SIDX);

    #pragma unroll 1
    for (int j = warp; j < NN; j += NWARP) {
        float* o = out + ((size_t)i * NN + j) * DIM + lane;
        if (smk[j] == 0.0f) { *o = 0.0f; continue; }   // warp-uniform
        const int s = soff[j];
        const int e = soff[j + 1];         // e-s is a multiple of 4
        float a0 = 0.f, a1 = 0.f, a2 = 0.f, a3 = 0.f;
        #pragma unroll 1
        for (int p = s; p < e; p += 4) {
            int4 k = *(const int4*)(sidx + p);         // aligned LDS.128
            a0 += sX[k.x + lane];
            a1 += sX[k.y + lane];
            a2 += sX[k.z + lane];
            a3 += sX[k.w + lane];
        }
        *o = (a0 + a1) + (a2 + a3);
    }
}

// ---------------------------------------------------------------------------
// Fused NGNN conv, MLP-first:
//   tX = (X@W + b) on active rows (zeros elsewhere);  ret[j] = m[j]*gather(tX)
// One CTA per subgraph i, 1024 threads, 2 phases, 2 barriers.
// ---------------------------------------------------------------------------
__global__ void __launch_bounds__(NTHR, 1)
ngnn_kernel(const float* __restrict__ X, const int* __restrict__ mask,
            const float* __restrict__ W, const float* __restrict__ b,
            float* __restrict__ out) {
    float* sX  = smem + OFF_SX;
    float* smk = smem + OFF_SMK;
    float* sW  = smem + OFF_SW;
    int*   soff = (int*)(smem + OFF_SOFF);
    int*   sidx = (int*)(smem + OFF_SIDX);

    const int tid  = threadIdx.x;
    const int lane = tid & 31;
    const int warp = tid >> 5;
    const int i    = blockIdx.x;

    const float breg = __ldg(&b[lane]);

    // ---- Stage mask, W, padded CSR; zero the dummy row ----
    smk[tid] = (float)mask[i * NN + tid];
    sW[tid]  = __ldg(&W[tid]);
    if (tid < DIM) sX[ZROW + tid] = 0.0f;
    for (int t = tid; t <= NN; t += NTHR) soff[t] = g_offsets[t];
    {
        const int EP = g_offsets[NN];      // padded edge count (mult of 4)
        const int4* gci = (const int4*)g_colidx;
        int4* sci = (int4*)sidx;
        for (int q = tid; q < (EP >> 2); q += NTHR) sci[q] = gci[q];
    }
    __syncthreads();

    // ---- Stage X[i] masked; skip the global load when m[k]==0 ----
    {
        const float4* Xg  = (const float4*)(X + (size_t)i * NN * DIM);
        float4* sX4 = (float4*)sX;
        #pragma unroll
        for (int q = 0; q < (NN * DIM / 4) / NTHR; q++) {
            int f = tid + q * NTHR;        // f = row*8 + slot
            float4 v = make_float4(0.f, 0.f, 0.f, 0.f);
            if (smk[f >> 3] != 0.0f) v = Xg[f];    // predicated LDG
            sX4[f] = v;
        }
    }
    __syncthreads();

    phase_mlp(lane, warp, breg);
    __syncthreads();
    phase_gather(out, i, lane, warp);
}

// ---------------------------------------------------------------------------
// Inputs: X, mask, edge_row, edge_col, W, b ; output f32
// ---------------------------------------------------------------------------
extern "C" void kernel_launch(void* const* d_in, const int* in_sizes, int n_in,
                              void* d_out, int out_size) {
    const float* X    = (const float*)d_in[0];
    const int*   mask = (const int*)d_in[1];
    const int*   erow = (const int*)d_in[2];
    const int*   ecol = (const int*)d_in[3];
    const float* W    = (const float*)d_in[4];
    const float* b    = (const float*)d_in[5];
    float*       out  = (float*)d_out;
    const int E = in_sizes[2];

    const int smem_bytes = SMEM_FLOATS * 4;    // ~188.7 KB
    cudaFuncSetAttribute(ngnn_kernel,
                         cudaFuncAttributeMaxDynamicSharedMemorySize, smem_bytes);

    build_csr_kernel<<<1, NN>>>(erow, ecol, E);
    ngnn_kernel<<<NN, NTHR, smem_bytes>>>(X, mask, W, b, out);
}

// round 11
// speedup vs baseline: 1.0127x; 1.0127x over previous
#include <cuda_runtime.h>

// Bench shape: N=1024, IND=OUTD=32, E=8192
#define NN    1024
#define DIM   32
#define EBASE 8192
#define EMAXP (EBASE + 3 * NN)     // padded-CSR worst case (rows rounded to 4)
#define NTHR  1024
#define NWARP 32
#define ZROW  (NN * DIM)           // dummy (always-zero) row offset (scaled)

// Shared-memory layout (float-index offsets into one dynamic allocation)
#define OFF_SX   0                            // [32800] tX rows + zero row
#define OFF_SMK  32800                        // [1056] mask
#define OFF_SW   (OFF_SMK + 1056)             // [1024] W copy
#define OFF_SOFF (OFF_SW + 1024)              // [1032] (int) CSR offsets
#define OFF_SIDX (OFF_SOFF + 1032)            // [EMAXP] (int) colidx*DIM
#define SMEM_FLOATS (OFF_SIDX + EMAXP)        // 47176 floats ≈ 188.7 KB

extern __shared__ float smem[];

// CSR scratch (device globals: allocation is forbidden)
__device__ int g_offsets[NN + 1];
__device__ int g_colidx[EMAXP];    // col * DIM (dummy pad -> ZROW)

// ---- packed f32x2 helpers (Blackwell; ptxas won't auto-fuse) --------------
__device__ __forceinline__ unsigned long long pack_f2(float lo, float hi) {
    unsigned long long r;
    asm("mov.b64 %0, {%1, %2};" : "=l"(r) : "f"(lo), "f"(hi));
    return r;
}
__device__ __forceinline__ void ffma2(unsigned long long& d,
                                      unsigned long long a,
                                      unsigned long long b) {
    asm("fma.rn.f32x2 %0, %1, %2, %0;" : "+l"(d) : "l"(a), "l"(b));
}
__device__ __forceinline__ float hsum_f2(unsigned long long v) {
    float lo, hi;
    asm("mov.b64 {%0, %1}, %2;" : "=f"(lo), "=f"(hi) : "l"(v));
    return lo + hi;
}

// ---------------------------------------------------------------------------
// Destination-keyed CSR, rows padded to multiples of 4 with dummy index ZROW.
// ---------------------------------------------------------------------------
__global__ void build_csr_kernel(const int* __restrict__ erow,
                                 const int* __restrict__ ecol, int E) {
    __shared__ int scnt[NN];
    __shared__ int sscan[NN];
    __shared__ int scur[NN];
    const int t = threadIdx.x;

    scnt[t] = 0;
    __syncthreads();
    for (int e = t; e < E; e += NN) atomicAdd(&scnt[erow[e]], 1);
    __syncthreads();

    const int padded = (scnt[t] + 3) & ~3;
    sscan[t] = padded;
    __syncthreads();
    #pragma unroll
    for (int d = 1; d < NN; d <<= 1) {
        int x = sscan[t];
        int y = (t >= d) ? sscan[t - d] : 0;
        __syncthreads();
        sscan[t] = x + y;
        __syncthreads();
    }
    const int incl = sscan[t];
    g_offsets[t + 1] = incl;
    if (t == 0) g_offsets[0] = 0;
    scur[t] = incl - padded;
    __syncthreads();

    for (int e = t; e < E; e += NN) {
        int r = erow[e];
        int p = atomicAdd(&scur[r], 1);
        g_colidx[p] = ecol[e] * DIM;
    }
    __syncthreads();
    for (int p = scur[t]; p < incl; p++) g_colidx[p] = ZROW;
}

// ---------------------------------------------------------------------------
// Phase 1 (own frame): tX[r] = X[r]@W + b  in place, active rows only.
// Warp-per-row, lane-per-output, broadcast LDS.128 + packed FFMA2.
// Masked rows stay exactly zero, so the gather's bias term
// b * (sum_e m[col]) emerges automatically.
// ---------------------------------------------------------------------------
__device__ __noinline__ void phase_mlp(int lane, int warp, float breg) {
    float*       sX  = smem + OFF_SX;
    const float* smk = smem + OFF_SMK;
    const float* sW  = smem + OFF_SW;

    unsigned long long wp[DIM / 2];        // 32 regs, live only in this frame
    #pragma unroll
    for (int q = 0; q < DIM / 2; q++)
        wp[q] = pack_f2(sW[(2 * q) * DIM + lane], sW[(2 * q + 1) * DIM + lane]);

    #pragma unroll 1
    for (int r = warp; r < NN; r += NWARP) {
        if (smk[r] == 0.0f) continue;      // warp-uniform skip
        const ulonglong2* xr = (const ulonglong2*)(sX + r * DIM);
        unsigned long long a0 = 0ULL, a1 = 0ULL;
        #pragma unroll
        for (int q = 0; q < 8; q++) {
            ulonglong2 v = xr[q];          // broadcast LDS.128
            ffma2(a0, v.x, wp[2 * q]);
            ffma2(a1, v.y, wp[2 * q + 1]);
        }
        float val = hsum_f2(a0) + hsum_f2(a1) + breg;
        __syncwarp();                      // all lanes done reading row r
        sX[r * DIM + lane] = val;          // in-place overwrite
    }
}

// ---------------------------------------------------------------------------
// Phase 2 (own frame): out[i,j] = m[j] * sum_e tX[col_e]
// Warp-per-j, lane-per-dim, 4-unrolled gathers (dummy edges hit zero row).
// ---------------------------------------------------------------------------
__device__ __noinline__ void phase_gather(float* __restrict__ out, int i,
                                          int lane, int warp) {
    const float* sX   = smem + OFF_SX;
    const float* smk  = smem + OFF_SMK;
    const int*   soff = (const int*)(smem + OFF_SOFF);
    const int*   sidx = (const int*)(smem + OFF_SIDX);

    #pragma unroll 1
    for (int j = warp; j < NN; j += NWARP) {
        float* o = out + ((size_t)i * NN + j) * DIM + lane;
        if (smk[j] == 0.0f) { *o = 0.0f; continue; }   // warp-uniform
        const int s = soff[j];
        const int e = soff[j + 1];         // e-s is a multiple of 4
        float a0 = 0.f, a1 = 0.f, a2 = 0.f, a3 = 0.f;
        #pragma unroll 1
        for (int p = s; p < e; p += 4) {
            int4 k = *(const int4*)(sidx + p);         // aligned LDS.128
            a0 += sX[k.x + lane];
            a1 += sX[k.y + lane];
            a2 += sX[k.z + lane];
            a3 += sX[k.w + lane];
        }
        *o = (a0 + a1) + (a2 + a3);
    }
}

// ---------------------------------------------------------------------------
// Fused NGNN conv, MLP-first:
//   tX = (X@W + b) on active rows (zeros elsewhere);  ret[j] = m[j]*gather(tX)
// One CTA per subgraph i, 1024 threads, 2 phases, 2 barriers.
// ---------------------------------------------------------------------------
__global__ void __launch_bounds__(NTHR, 1)
ngnn_kernel(const float* __restrict__ X, const int* __restrict__ mask,
            const float* __restrict__ W, const float* __restrict__ b,
            float* __restrict__ out) {
    float* sX  = smem + OFF_SX;
    float* smk = smem + OFF_SMK;
    float* sW  = smem + OFF_SW;
    int*   soff = (int*)(smem + OFF_SOFF);
    int*   sidx = (int*)(smem + OFF_SIDX);

    const int tid  = threadIdx.x;
    const int lane = tid & 31;
    const int warp = tid >> 5;
    const int i    = blockIdx.x;

    const float breg = __ldg(&b[lane]);

    // ---- Stage mask, W, padded CSR; zero the dummy row ----
    smk[tid] = (float)mask[i * NN + tid];
    sW[tid]  = __ldg(&W[tid]);
    if (tid < DIM) sX[ZROW + tid] = 0.0f;
    for (int t = tid; t <= NN; t += NTHR) soff[t] = g_offsets[t];
    {
        const int EP = g_offsets[NN];      // padded edge count (mult of 4)
        const int4* gci = (const int4*)g_colidx;
        int4* sci = (int4*)sidx;
        for (int q = tid; q < (EP >> 2); q += NTHR) sci[q] = gci[q];
    }
    __syncthreads();

    // ---- Stage X[i] masked; skip the global load when m[k]==0 ----
    {
        const float4* Xg  = (const float4*)(X + (size_t)i * NN * DIM);
        float4* sX4 = (float4*)sX;
        #pragma unroll
        for (int q = 0; q < (NN * DIM / 4) / NTHR; q++) {
            int f = tid + q * NTHR;        // f = row*8 + slot
            float4 v = make_float4(0.f, 0.f, 0.f, 0.f);
            if (smk[f >> 3] != 0.0f) v = Xg[f];    // predicated LDG
            sX4[f] = v;
        }
    }
    __syncthreads();

    phase_mlp(lane, warp, breg);
    __syncthreads();
    phase_gather(out, i, lane, warp);
}

// ---------------------------------------------------------------------------
// Inputs: X, mask, edge_row, edge_col, W, b ; output f32
// ---------------------------------------------------------------------------
extern "C" void kernel_launch(void* const* d_in, const int* in_sizes, int n_in,
                              void* d_out, int out_size) {
    const float* X    = (const float*)d_in[0];
    const int*   mask = (const int*)d_in[1];
    const int*   erow = (const int*)d_in[2];
    const int*   ecol = (const int*)d_in[3];
    const float* W    = (const float*)d_in[4];
    const float* b    = (const float*)d_in[5];
    float*       out  = (float*)d_out;
    const int E = in_sizes[2];

    const int smem_bytes = SMEM_FLOATS * 4;    // ~188.7 KB
    cudaFuncSetAttribute(ngnn_kernel,
                         cudaFuncAttributeMaxDynamicSharedMemorySize, smem_bytes);

    build_csr_kernel<<<1, NN>>>(erow, ecol, E);
    ngnn_kernel<<<NN, NTHR, smem_bytes>>>(X, mask, W, b, out);
}